// round 17
// baseline (speedup 1.0000x reference)
#include <cuda_runtime.h>
#include <cuda_fp16.h>

#define NPTS   50000
#define NEDGE  800000
#define NT16   50000      // 16 edges per warp-tile
#define GRID   444
#define NWTOT  (GRID * 8)         // 3552 warps
#define KSTAT  14                 // static tiles per warp
#define TAIL0  (NWTOT * KSTAT)    // 49728

__device__ int g_is64;
__device__ int g_tailctr;

#define SWZ(b) ((b) ^ (((b) >> 3) & 0x70))

__device__ __forceinline__ unsigned smem_u32(const void* p) {
    unsigned a;
    asm("{ .reg .u64 t; cvta.to.shared.u64 t, %1; cvt.u32.u64 %0, t; }" : "=r"(a) : "l"(p));
    return a;
}

#define LDSM2(r0, r1, addr) \
    asm volatile("ldmatrix.sync.aligned.m8n8.x2.shared.b16 {%0,%1}, [%2];" \
        : "=r"(r0), "=r"(r1) : "r"(addr))

#define LDSM4(r0, r1, r2, r3, addr) \
    asm volatile("ldmatrix.sync.aligned.m8n8.x4.shared.b16 {%0,%1,%2,%3}, [%4];" \
        : "=r"(r0), "=r"(r1), "=r"(r2), "=r"(r3) : "r"(addr))

#define MMA16816(d, a0, a1, a2, a3, b0, b1) \
    asm volatile("mma.sync.aligned.m16n8k16.row.col.f32.f16.f16.f32 " \
        "{%0,%1,%2,%3}, {%4,%5,%6,%7}, {%8,%9}, {%0,%1,%2,%3};" \
        : "+f"((d)[0]), "+f"((d)[1]), "+f"((d)[2]), "+f"((d)[3]) \
        : "r"(a0), "r"(a1), "r"(a2), "r"(a3), "r"(b0), "r"(b1))

#define MMA16808(d, a0, a1, b0) \
    asm volatile("mma.sync.aligned.m16n8k8.row.col.f32.f16.f16.f32 " \
        "{%0,%1,%2,%3}, {%4,%5}, {%6}, {%0,%1,%2,%3};" \
        : "+f"((d)[0]), "+f"((d)[1]), "+f"((d)[2]), "+f"((d)[3]) \
        : "r"(a0), "r"(a1), "r"(b0))

#define CP_ASYNC16(smem, gmem) \
    asm volatile("cp.async.ca.shared.global [%0], [%1], 16;" \
        :: "r"(smem), "l"(gmem) : "memory")
#define CP_COMMIT() asm volatile("cp.async.commit_group;" ::: "memory")

// Vector reduction (PTX ISA 8.1+, sm_90+): one instruction, 8B per lane.
#define RED2(ptr, a, b) \
    asm volatile("red.global.add.v2.f32 [%0], {%1, %2};" \
        :: "l"(ptr), "f"(a), "f"(b) : "memory")

// Branchless gelu, erf via A-S 7.1.25 (3-term, |eps|<=2.5e-5, far below fp16 rounding).
__device__ __forceinline__ float gelu_fast(float x) {
    float t = fabsf(x) * 0.70710678118654752440f;
    float k = __fdividef(1.0f, fmaf(0.47047f, t, 1.0f));
    float p = fmaf(fmaf(0.7478556f, k, -0.0958798f), k, 0.3480242f) * k;
    float e = __expf(-t * t);
    float erf = fmaf(-p, e, 1.0f);
    float phi = fmaf(copysignf(erf, x), 0.5f, 0.5f);
    return x * phi;
}
__device__ __forceinline__ unsigned h2u(float a, float b) {
    __half2 h = __floats2half2_rn(a, b);
    return *(unsigned*)&h;
}
__device__ __forceinline__ unsigned gelu2_pack(float a, float b) {
    return h2u(gelu_fast(a), gelu_fast(b));
}

// -------- init: dtype detect + zero out + tail counter reset --------
__global__ __launch_bounds__(256) void init_kernel(
    const int* __restrict__ ei32, float* __restrict__ out)
{
    int t = blockIdx.x * blockDim.x + threadIdx.x;
    if (blockIdx.x == 0 && threadIdx.x < 32) {
        int lane = threadIdx.x;
        int nz = (ei32[2 * lane + 1] != 0) || (ei32[2 * (lane + 32) + 1] != 0);
        unsigned any = __ballot_sync(0xffffffffu, nz);
        if (lane == 0) g_is64 = (any == 0u);
    }
    if (blockIdx.x == 0 && threadIdx.x == 32) g_tailctr = TAIL0;
    if (t < NPTS * 16) out[t] = 0.0f;
}

// -------- edge kernel: m16 warp-tiles, 3 CTAs/SM, cp.async prefetch, tail pool ----
__global__ __launch_bounds__(256, 3) void edge_kernel(
    const float* __restrict__ x, const float* __restrict__ pos,
    const int* __restrict__ ei,
    const float* __restrict__ W1, const float* __restrict__ b1,
    const float* __restrict__ bh, const float* __restrict__ Wh,
    const float* __restrict__ Wo, const float* __restrict__ bo,
    float* __restrict__ out)
{
    extern __shared__ char dyn[];
    __shared__ float sbh[64];
    __shared__ float sbo[256];
    __shared__ unsigned sW1f[8 * 32];
    __shared__ float sx[2][128 * 20];      // fp32 x, stride 20 (conflict-free, 16B-aligned)
    __shared__ __align__(16) uint4 spe[128];

    unsigned dbase = smem_u32(dyn);
    unsigned abase = (dbase + 1023u) & ~1023u;
    char* sp = dyn + (abase - dbase);
    const unsigned WH_OFF = 0, WO_OFF = 8192;
    unsigned WHs = abase + WH_OFF, WOs = abase + WO_OFF;

    int tid = threadIdx.x, lane = tid & 31, wid = tid >> 5;
    const unsigned F = 0xffffffffu;

    if (tid < 64) sbh[tid] = bh[tid];
    if (tid < 256) sbo[tid] = bo[tid];
    if (tid < 32) {      // W1 B-frags (k8n8), bias folded as row 6 (pe[6]=1), row 7 = 0
        int lg = tid >> 2, ltig = tid & 3;
        #pragma unroll
        for (int nt = 0; nt < 8; nt++) {
            int c = nt * 8 + lg;
            sW1f[nt * 32 + tid] = (ltig == 3)
                ? h2u(__ldg(&b1[c]), 0.0f)
                : h2u(__ldg(&W1[(2 * ltig) * 64 + c]), __ldg(&W1[(2 * ltig + 1) * 64 + c]));
        }
    }
    // WhT[c][j] = Wh[j*64+c]  fp16 K-major rows of 128B, SW128
    for (int t = tid; t < 4096; t += 256) {
        int j = t >> 6, c = t & 63;
        *(__half*)(sp + WH_OFF + SWZ(c * 128 + j * 2)) = __float2half_rn(Wh[t]);
    }
    // WoT[p][j] = Wo[j*256+p]
    for (int t = tid; t < 16384; t += 256) {
        int j = t >> 8, p = t & 255;
        *(__half*)(sp + WO_OFF + SWZ(p * 128 + j * 2)) = __float2half_rn(Wo[t]);
    }
    __syncthreads();

    const int is64 = g_is64;
    const int g = lane >> 2, tig = lane & 3;
    const int wb = wid * 16;
    const int er = lane & 15;               // edge slot within tile
    const int xrow = lane >> 1, xh = lane & 1;   // x staging: 2 lanes per row

    // hoisted swizzled B-address bases (1024-multiple row offsets add linearly)
    unsigned wh_a = WHs + SWZ((unsigned)(lane & 7) * 128 + (lane >> 3) * 16);
    unsigned wh_b = WHs + SWZ((unsigned)(lane & 7) * 128 + (4 + (lane >> 3)) * 16);
    unsigned wo_a = WOs + SWZ((unsigned)(lane & 7) * 128 + (lane >> 3) * 16);
    unsigned wo_b = WOs + SWZ((unsigned)(lane & 7) * 128 + (4 + (lane >> 3)) * 16);
    unsigned pe_addr = smem_u32(spe) + (unsigned)(wb + er) * 16;
    unsigned sx_u = smem_u32(sx);

    int gw = blockIdx.x * 8 + wid;
    int nw = NWTOT;

    int dcur;    // dst of this warp's current tile, edge `er`, kept in-register

    // ---- prologue: stage tile gw into parity 0 ----
    {
        int e0 = gw * 16 + er;
        int s0;
        if (is64) { s0 = ei[2 * e0]; dcur = ei[2 * NEDGE + 2 * e0]; }
        else      { s0 = ei[e0];     dcur = ei[NEDGE + e0]; }
        uint4 pev;
        pev.x = h2u(__ldg(&pos[s0 * 3 + 0]), __ldg(&pos[s0 * 3 + 1]));
        pev.y = h2u(__ldg(&pos[s0 * 3 + 2]), __ldg(&pos[dcur * 3 + 0]));
        pev.z = h2u(__ldg(&pos[dcur * 3 + 1]), __ldg(&pos[dcur * 3 + 2]));
        pev.w = h2u(1.0f, 0.0f);
        spe[wb + er] = pev;
        int s2 = __shfl_sync(F, s0, xrow);
        const char* gx = (const char*)(x + (size_t)s2 * 16 + xh * 8);
        unsigned sa = sx_u + (unsigned)((wb + xrow) * 20 + xh * 8) * 4;
        CP_ASYNC16(sa, gx);
        CP_ASYNC16(sa + 16, gx + 16);
        CP_COMMIT();
    }

    int t = gw, k = 1, p = 0;
    while (true) {
        int t2;
        if (k < KSTAT) {
            t2 = t + nw;                          // static schedule: gw + k*nw
        } else {
            // warp-uniform tail pull: ONE atomic per warp, broadcast to all lanes
            if (lane == 0) {
                t2 = atomicAdd(&g_tailctr, 1);
                if (t2 >= NT16) t2 = -1;
            }
            t2 = __shfl_sync(F, t2, 0);
        }
        const bool hn = (t2 >= 0);
        int pfs = 0, pfd = 0;
        if (hn) {
            int e2 = t2 * 16 + er;
            if (is64) { pfs = ei[2 * e2]; pfd = ei[2 * NEDGE + 2 * e2]; }
            else      { pfs = ei[e2];     pfd = ei[NEDGE + e2]; }
        }
        __syncwarp();

        // ---- MMA1: h1 = gelu(pe @ [W1;b1;0]) ----
        unsigned pA0, pA1;
        LDSM2(pA0, pA1, pe_addr);

        unsigned h1f[4][4];
        #pragma unroll
        for (int kc = 0; kc < 4; kc++)
            #pragma unroll
            for (int par = 0; par < 2; par++) {
                unsigned b = sW1f[(2 * kc + par) * 32 + lane];
                float d[4] = {0.0f, 0.0f, 0.0f, 0.0f};
                MMA16808(d, pA0, pA1, b);
                h1f[kc][2 * par]     = gelu2_pack(d[0], d[1]);
                h1f[kc][2 * par + 1] = gelu2_pack(d[2], d[3]);
            }

        // ---- stage next tile (phase 1): pos LDGs + x via cp.async ----
        float pp0, pp1, pp2, pp3, pp4, pp5;
        if (hn) {
            pp0 = __ldg(&pos[pfs * 3 + 0]); pp1 = __ldg(&pos[pfs * 3 + 1]);
            pp2 = __ldg(&pos[pfs * 3 + 2]);
            pp3 = __ldg(&pos[pfd * 3 + 0]); pp4 = __ldg(&pos[pfd * 3 + 1]);
            pp5 = __ldg(&pos[pfd * 3 + 2]);
            int s2 = __shfl_sync(F, pfs, xrow);
            const char* gx = (const char*)(x + (size_t)s2 * 16 + xh * 8);
            unsigned sa = sx_u + (unsigned)((p ^ 1) * 2560 + (wb + xrow) * 20 + xh * 8) * 4;
            CP_ASYNC16(sa, gx);
            CP_ASYNC16(sa + 16, gx + 16);
            CP_COMMIT();
        }

        // ---- MMA2: h2 = gelu(h1 @ Wh + bh), split accumulator chains ----
        unsigned h2f[4][4];
        #pragma unroll
        for (int kc = 0; kc < 4; kc++)
            #pragma unroll
            for (int par = 0; par < 2; par++) {
                int nt = 2 * kc + par;
                unsigned b0, b1r, b2, b3, b4, b5, b6, b7;
                LDSM4(b0, b1r, b2, b3, wh_a + (unsigned)nt * 1024);
                LDSM4(b4, b5, b6, b7, wh_b + (unsigned)nt * 1024);
                float2 bh2 = *(const float2*)&sbh[nt * 8 + 2 * tig];
                float d[4]  = {bh2.x, bh2.y, bh2.x, bh2.y};
                float d2[4] = {0.0f, 0.0f, 0.0f, 0.0f};
                MMA16816(d,  h1f[0][0], h1f[0][1], h1f[0][2], h1f[0][3], b0, b1r);
                MMA16816(d2, h1f[1][0], h1f[1][1], h1f[1][2], h1f[1][3], b2, b3);
                MMA16816(d,  h1f[2][0], h1f[2][1], h1f[2][2], h1f[2][3], b4, b5);
                MMA16816(d2, h1f[3][0], h1f[3][1], h1f[3][2], h1f[3][3], b6, b7);
                h2f[kc][2 * par]     = gelu2_pack(d[0] + d2[0], d[1] + d2[1]);
                h2f[kc][2 * par + 1] = gelu2_pack(d[2] + d2[2], d[3] + d2[3]);
            }

        // ---- stage next tile (phase 2): pack + store pe ----
        if (hn) {
            uint4 pev;
            pev.x = h2u(pp0, pp1); pev.y = h2u(pp2, pp3);
            pev.z = h2u(pp4, pp5); pev.w = h2u(1.0f, 0.0f);
            spe[wb + er] = pev;    // safe: this tile's pe LDSM already done
        }

        // ---- wait for this tile's x (issued last iteration / prologue) ----
        if (hn) { asm volatile("cp.async.wait_group 1;" ::: "memory"); }
        else    { asm volatile("cp.async.wait_group 0;" ::: "memory"); }
        __syncwarp();

        // ---- MMA3: z = h2 @ Wo + bo; fold x-contraction; float4 x loads per ch ----
        const float* sxp = &sx[p][0];
        float msg[8];
        #pragma unroll
        for (int q = 0; q < 8; q++) msg[q] = 0.0f;

        #pragma unroll
        for (int ch = 0; ch < 4; ch++) {
            float4 xva = *(const float4*)&sxp[(wb + g) * 20 + 4 * ch];       // x[row g, 4ch..4ch+3]
            float4 xvb = *(const float4*)&sxp[(wb + g + 8) * 20 + 4 * ch];   // x[row g+8, ...]
            const float xar[4] = {xva.x, xva.y, xva.z, xva.w};
            const float xbr[4] = {xvb.x, xvb.y, xvb.z, xvb.w};
            #pragma unroll
            for (int ntp = 0; ntp < 4; ntp++) {
                unsigned prow0 = (unsigned)(ch * 64 + ntp * 16) * 128;
                unsigned prow1 = prow0 + 1024;
                unsigned b0, b1r, b2, b3, b4, b5, b6, b7;
                unsigned c0, c1r, c2, c3, c4, c5, c6, c7;
                LDSM4(b0, b1r, b2, b3, wo_a + prow0);
                LDSM4(b4, b5, b6, b7, wo_b + prow0);
                LDSM4(c0, c1r, c2, c3, wo_a + prow1);
                LDSM4(c4, c5, c6, c7, wo_b + prow1);
                int cbase = ch * 64 + ntp * 16 + 2 * tig;
                float2 bz0 = *(const float2*)&sbo[cbase];
                float2 bz1 = *(const float2*)&sbo[cbase + 8];
                float xa = xar[ntp];
                float xb = xbr[ntp];
                float d0[4] = {bz0.x, bz0.y, bz0.x, bz0.y};
                float d1[4] = {bz1.x, bz1.y, bz1.x, bz1.y};
                MMA16816(d0, h2f[0][0], h2f[0][1], h2f[0][2], h2f[0][3], b0, b1r);
                MMA16816(d1, h2f[0][0], h2f[0][1], h2f[0][2], h2f[0][3], c0, c1r);
                MMA16816(d0, h2f[1][0], h2f[1][1], h2f[1][2], h2f[1][3], b2, b3);
                MMA16816(d1, h2f[1][0], h2f[1][1], h2f[1][2], h2f[1][3], c2, c3);
                MMA16816(d0, h2f[2][0], h2f[2][1], h2f[2][2], h2f[2][3], b4, b5);
                MMA16816(d1, h2f[2][0], h2f[2][1], h2f[2][2], h2f[2][3], c4, c5);
                MMA16816(d0, h2f[3][0], h2f[3][1], h2f[3][2], h2f[3][3], b6, b7);
                MMA16816(d1, h2f[3][0], h2f[3][1], h2f[3][2], h2f[3][3], c6, c7);
                msg[0] += d0[0] * xa;  msg[1] += d0[1] * xa;
                msg[4] += d0[2] * xb;  msg[5] += d0[3] * xb;
                msg[2] += d1[0] * xa;  msg[3] += d1[1] * xa;
                msg[6] += d1[2] * xb;  msg[7] += d1[3] * xb;
            }
        }

        // ---- scatter: dst via register shuffle (lane e holds dst of edge e) ----
        int dA = __shfl_sync(F, dcur, g);
        int dB = __shfl_sync(F, dcur, g + 8);
        float* pA = out + (size_t)dA * 16 + 2 * tig;
        float* pB = out + (size_t)dB * 16 + 2 * tig;
        RED2(pA,     msg[0], msg[1]);
        RED2(pA + 8, msg[2], msg[3]);
        RED2(pB,     msg[4], msg[5]);
        RED2(pB + 8, msg[6], msg[7]);

        if (!hn) break;
        t = t2; k++; p ^= 1; dcur = pfd;
    }
}

extern "C" void kernel_launch(void* const* d_in, const int* in_sizes, int n_in,
                              void* d_out, int out_size) {
    const float* x   = (const float*)d_in[0];
    const float* pos = (const float*)d_in[1];
    const int*   ei  = (const int*)d_in[2];
    const float* W1  = (const float*)d_in[3];
    const float* b1  = (const float*)d_in[4];
    const float* Wh  = (const float*)d_in[5];
    const float* bh  = (const float*)d_in[6];
    const float* Wo  = (const float*)d_in[7];
    const float* bo  = (const float*)d_in[8];
    float* out = (float*)d_out;

    cudaFuncSetAttribute(edge_kernel, cudaFuncAttributeMaxDynamicSharedMemorySize, 41984);

    init_kernel<<<(NPTS * 16 + 255) / 256, 256>>>(ei, out);
    edge_kernel<<<GRID, 256, 41984>>>(x, pos, ei, W1, b1, bh, Wh, Wo, bo, out);
}